// round 10
// baseline (speedup 1.0000x reference)
#include <cuda_runtime.h>
#include <math.h>
#include <stdint.h>

// ---------------- problem dims ----------------
#define cB   256
#define cN   2048
#define cD   128
#define cR   4
#define cH   1024
#define cI   1024
#define cCI  1536
#define cIF  787
#define cOPI 1536
#define cG   4096   // 4*H

// ---------------- scratch (device globals) ----------------
__device__ float g_mean_mem[cD];
__device__ float g_v[cG];
__device__ float g_graw[cB * cG];
__device__ float g_itf[cB * cIF];
__device__ float g_wvn[cB * cD];
__device__ float g_wg[cB];
__device__ float g_ag[cB];
__device__ float g_rm[cB * cR * 3];
__device__ float g_keys[cB * cR * cD];
__device__ float g_memn[cN * cD];
__device__ float g_cw[cB * cN];
__device__ float g_alloc[cN];
__device__ float g_sorted[cN];
__device__ int   g_sidx[cN];
__device__ float g_ww[cB * cN];
__device__ float g_wwT[cN * cB];
__device__ float g_S[cB];
__device__ float g_rowsum[cN];
__device__ float g_colsum[cN];
__device__ float g_bvec[cN];
__device__ float g_fvec[cN];
__device__ float g_evav[cB * 2 * cD];     // [b][0:128)=ev, [128:256)=av
__device__ float g_evavT[2 * cD * cB];
__device__ float g_eamat[cN * 2 * cD];    // [n][0:128)=emat, [128:256)=amat
__device__ float g_memnew[cN * cD];
__device__ float g_memnewn[cN * cD];
__device__ float g_memnewT[cD * cN];
__device__ float g_bm[cD];
__device__ float g_fm[cD];
__device__ float g_L[cB * cR * cN];
__device__ float g_readc[cB * cR * cD];
__device__ float g_cat[cB * cOPI];        // [h | readout]

// ---------------- helpers ----------------
__device__ __forceinline__ float sigmoidf_(float x) { return 1.0f / (1.0f + expf(-x)); }
__device__ __forceinline__ float softplusf_(float x) { return x > 20.0f ? x : log1pf(expf(x)); }
__device__ __forceinline__ uint32_t f2tf32(float f) {
    uint32_t u; asm("cvt.rna.tf32.f32 %0, %1;" : "=r"(u) : "f"(f)); return u;
}
__device__ __forceinline__ void mma8(float* c, const uint32_t* a, const uint32_t* b) {
    asm volatile(
        "mma.sync.aligned.m16n8k8.row.col.f32.tf32.tf32.f32 "
        "{%0,%1,%2,%3},{%4,%5,%6,%7},{%8,%9},{%0,%1,%2,%3};"
        : "+f"(c[0]), "+f"(c[1]), "+f"(c[2]), "+f"(c[3])
        : "r"(a[0]), "r"(a[1]), "r"(a[2]), "r"(a[3]), "r"(b[0]), "r"(b[1]));
}

// ================= tf32 tensor-core GEMM (nt): C[M,N] = A[M,K] . B[N,K]^T =================
#define MMA_SMEM (2*(128*36 + 64*36)*4)

template<int SPLITK, bool ATOMIC>
__global__ void mma_nt(const float* __restrict__ A, int lda,
                       const float* __restrict__ Bm, int ldb,
                       const float* __restrict__ bias,
                       float* __restrict__ C, int ldc,
                       int M, int N, int K)
{
    extern __shared__ float sm_[];
    float* As = sm_;                 // [2][128][36]
    float* Bs = sm_ + 2 * 128 * 36;  // [2][64][36]
    const int t = threadIdx.x;
    const int lane = t & 31;
    const int w = t >> 5;
    const int grp = lane >> 2, tg = lane & 3;
    const int wm = w & 3, wn = w >> 2;
    const int m0 = blockIdx.y * 128, n0 = blockIdx.x * 64;
    const int Kc = K / SPLITK;
    const int kstart = blockIdx.z * Kc;
    const int KT = Kc / 32;

    const uint32_t sA = (uint32_t)__cvta_generic_to_shared(As);
    const uint32_t sB = (uint32_t)__cvta_generic_to_shared(Bs);
    const int lr = t >> 3, lc = (t & 7) * 4;

    float acc[2][4][4];
#pragma unroll
    for (int mi = 0; mi < 2; mi++)
#pragma unroll
        for (int ni = 0; ni < 4; ni++)
#pragma unroll
            for (int k = 0; k < 4; k++) acc[mi][ni][k] = 0.f;

    auto load_stage = [&](int st, int kb) {
#pragma unroll
        for (int i = 0; i < 4; i++) {
            int row = lr + 32 * i;
            const float* g = A + (size_t)(m0 + row) * lda + kb + lc;
            uint32_t d = sA + (uint32_t)((st * 4608 + row * 36 + lc) * 4);
            asm volatile("cp.async.ca.shared.global [%0],[%1],16,%2;" :: "r"(d), "l"(g), "r"(16));
        }
#pragma unroll
        for (int i = 0; i < 2; i++) {
            int row = lr + 32 * i;
            const float* g = Bm + (size_t)(n0 + row) * ldb + kb + lc;
            uint32_t d = sB + (uint32_t)((st * 2304 + row * 36 + lc) * 4);
            int sz = (n0 + row < N) ? 16 : 0;
            asm volatile("cp.async.ca.shared.global [%0],[%1],16,%2;" :: "r"(d), "l"(g), "r"(sz));
        }
        asm volatile("cp.async.commit_group;");
    };

    auto compute = [&](int st) {
        const float* Ab = As + st * 4608;
        const float* Bb = Bs + st * 2304;
#pragma unroll
        for (int ko = 0; ko < 32; ko += 8) {
            uint32_t af[2][4], bf[4][2];
#pragma unroll
            for (int mi = 0; mi < 2; mi++) {
                int rb = wm * 32 + mi * 16;
                af[mi][0] = f2tf32(Ab[(rb + grp) * 36 + ko + tg]);
                af[mi][1] = f2tf32(Ab[(rb + grp + 8) * 36 + ko + tg]);
                af[mi][2] = f2tf32(Ab[(rb + grp) * 36 + ko + tg + 4]);
                af[mi][3] = f2tf32(Ab[(rb + grp + 8) * 36 + ko + tg + 4]);
            }
#pragma unroll
            for (int ni = 0; ni < 4; ni++) {
                int nb = wn * 32 + ni * 8 + grp;
                bf[ni][0] = f2tf32(Bb[nb * 36 + ko + tg]);
                bf[ni][1] = f2tf32(Bb[nb * 36 + ko + tg + 4]);
            }
#pragma unroll
            for (int mi = 0; mi < 2; mi++)
#pragma unroll
                for (int ni = 0; ni < 4; ni++) mma8(acc[mi][ni], af[mi], bf[ni]);
        }
    };

    load_stage(0, kstart);
    for (int kt = 0; kt < KT; kt++) {
        if (kt + 1 < KT) {
            load_stage((kt + 1) & 1, kstart + (kt + 1) * 32);
            asm volatile("cp.async.wait_group 1;");
        } else {
            asm volatile("cp.async.wait_group 0;");
        }
        __syncthreads();
        compute(kt & 1);
        __syncthreads();
    }

    const bool addb = (bias != nullptr) && (SPLITK == 1 || blockIdx.z == 0);
#pragma unroll
    for (int mi = 0; mi < 2; mi++) {
        int r_ = m0 + wm * 32 + mi * 16 + grp;
#pragma unroll
        for (int ni = 0; ni < 4; ni++) {
            int c_ = n0 + wn * 32 + ni * 8 + tg * 2;
            float b0 = (addb && c_ < N) ? bias[c_] : 0.f;
            float b1 = (addb && c_ + 1 < N) ? bias[c_ + 1] : 0.f;
            float* cp0 = C + (size_t)r_ * ldc + c_;
            float* cp1 = C + (size_t)(r_ + 8) * ldc + c_;
            if (ATOMIC) {
                if (c_ < N)     { atomicAdd(cp0,     acc[mi][ni][0] + b0);
                                  atomicAdd(cp1,     acc[mi][ni][2] + b0); }
                if (c_ + 1 < N) { atomicAdd(cp0 + 1, acc[mi][ni][1] + b1);
                                  atomicAdd(cp1 + 1, acc[mi][ni][3] + b1); }
            } else {
                if (c_ < N)     { cp0[0] = acc[mi][ni][0] + b0;
                                  cp1[0] = acc[mi][ni][2] + b0; }
                if (c_ + 1 < N) { cp0[1] = acc[mi][ni][1] + b1;
                                  cp1[1] = acc[mi][ni][3] + b1; }
            }
        }
    }
}

// ================= small kernels =================

// column mean of memory (before stage0; k_v depends on it)
__global__ void k_mem_mean(const float* __restrict__ memory) {
    int t = threadIdx.x;              // 256: d = t&127, half = t>>7
    int d = t & 127;
    int r0 = blockIdx.x * 64 + (t >> 7);   // 32 blocks
    float s = 0.f;
    for (int r = 0; r < 32; r++) s += memory[(size_t)(r0 + r * 2) * cD + d];
    atomicAdd(&g_mean_mem[d], s * (1.0f / (float)cN));
}

// fused stage-0: rank | memn | link rowsum | link colsum | v
#define S0_RANK 0
#define S0_NORM 256
#define S0_ROWS 1280
#define S0_COLS 1536
#define S0_V    1664
#define S0_END  2176
__global__ void k_stage0(const float* __restrict__ memory,
                         const float* __restrict__ link,
                         const float* __restrict__ usage,
                         const float* __restrict__ W_ih) {
    __shared__ float sh[8];
    int blk = blockIdx.x, t = threadIdx.x;
    int w = t >> 5, lane = t & 31;
    if (blk < S0_NORM) {
        // rank: warp per element (stable ascending)
        int e = blk * 8 + w;
        float u = usage[e];
        int r = 0;
        for (int j = lane; j < cN; j += 32) {
            float uj = usage[j];
            r += (uj < u) || (uj == u && j < e);
        }
#pragma unroll
        for (int o = 16; o; o >>= 1) r += __shfl_xor_sync(0xffffffffu, r, o);
        if (lane == 0) { g_sorted[r] = u; g_sidx[r] = e; }
    } else if (blk < S0_ROWS) {
        // normalize memory rows: 2 rows per block
        int rb = (blk - S0_NORM) * 2 + (t >> 7);
        int d = t & 127;
        float v = memory[(size_t)rb * cD + d];
        float sq = v * v;
#pragma unroll
        for (int o = 16; o; o >>= 1) sq += __shfl_xor_sync(0xffffffffu, sq, o);
        if (lane == 0) sh[w] = sq;
        __syncthreads();
        int base = (t >> 7) * 4;
        float tot = sh[base] + sh[base + 1] + sh[base + 2] + sh[base + 3];
        g_memn[(size_t)rb * cD + d] = v / fmaxf(sqrtf(tot), 1e-12f);
    } else if (blk < S0_COLS) {
        // link row sums: warp per row
        int row = (blk - S0_ROWS) * 8 + w;
        const float* p = link + (size_t)row * cN;
        float s = 0.f;
        for (int j = lane; j < cN; j += 32) s += p[j];
#pragma unroll
        for (int o = 16; o; o >>= 1) s += __shfl_xor_sync(0xffffffffu, s, o);
        if (lane == 0) g_rowsum[row] = s;
    } else if (blk < S0_V) {
        // link col sums: 128 blocks (16 row-chunks x 8 col-chunks)
        int rc = blk - S0_COLS;
        int rchunk = rc >> 3, cchunk = rc & 7;
        int col = cchunk * 256 + t;
        const float* p = link + (size_t)(rchunk * 128) * cN + col;
        float acc = 0.f;
        for (int r = 0; r < 128; r++) acc += p[(size_t)r * cN];
        atomicAdd(&g_colsum[col], acc);
    } else {
        // v[j] = mean_mem (tiled x4) . W_ih[j, 1024:1536]
        int gw = (blk - S0_V) * 8 + w;
        const float* wr = W_ih + (size_t)gw * cCI + cI;
        float a = 0.f;
        for (int k = lane; k < cR * cD; k += 32) a += g_mean_mem[k & (cD - 1)] * wr[k];
#pragma unroll
        for (int o = 16; o; o >>= 1) a += __shfl_xor_sync(0xffffffffu, a, o);
        if (lane == 0) g_v[gw] = a;
    }
}

// two-level multiplicative scan over sorted usage; scatter alloc
__global__ void k_scan() {
    __shared__ float wtot[32];
    int t = threadIdx.x;  // 1024
    int lane = t & 31, wid = t >> 5;
    float u0 = g_sorted[2 * t], u1 = g_sorted[2 * t + 1];
    float v0 = 1.0f - u0, v1 = 1.0f - u1;
    float p = v0 * v1;
    float sp = p;  // inclusive scan of pair products within warp
#pragma unroll
    for (int o = 1; o < 32; o <<= 1) {
        float n = __shfl_up_sync(0xffffffffu, sp, o);
        if (lane >= o) sp *= n;
    }
    if (lane == 31) wtot[wid] = sp;
    __syncthreads();
    if (wid == 0) {
        float wv = wtot[lane];
#pragma unroll
        for (int o = 1; o < 32; o <<= 1) {
            float n = __shfl_up_sync(0xffffffffu, wv, o);
            if (lane >= o) wv *= n;
        }
        wtot[lane] = wv;
    }
    __syncthreads();
    float eincl = __shfl_up_sync(0xffffffffu, sp, 1);     // exclusive pair prefix (within warp)
    float epair = (lane == 0) ? 1.0f : eincl;
    float wpre = (wid == 0) ? 1.0f : wtot[wid - 1];
    float E0 = wpre * epair;          // prod of (1-u) before index 2t
    float E1 = E0 * v0;               // before index 2t+1
    g_alloc[g_sidx[2 * t]]     = u0 * E0;
    g_alloc[g_sidx[2 * t + 1]] = u1 * E1;
}

// LSTM gates -> h written straight into g_cat[:, 0:1024]
__global__ void k_gates(const float* __restrict__ b_ih, const float* __restrict__ b_hh) {
    int idx = blockIdx.x * blockDim.x + threadIdx.x;
    if (idx >= cB * cH) return;
    int b = idx >> 10, j = idx & (cH - 1);
    const float* gr = g_graw + (size_t)b * cG;
    float gi = gr[j]          + b_ih[j]          + b_hh[j]          + g_v[j];
    float gg = gr[j + 2 * cH] + b_ih[j + 2 * cH] + b_hh[j + 2 * cH] + g_v[j + 2 * cH];
    float go = gr[j + 3 * cH] + b_ih[j + 3 * cH] + b_hh[j + 3 * cH] + g_v[j + 3 * cH];
    float c = sigmoidf_(gi) * tanhf(gg);
    g_cat[(size_t)b * cOPI + j] = sigmoidf_(go) * tanhf(c);
}

// fused: parse + softmax3 + wv-norm + key-norms(+strength) + evav; one block per b
__global__ void k_parse_fused(const float* __restrict__ b_if) {
    __shared__ float sv[cIF];
    __shared__ float red[8];
    __shared__ float srstr[4];
    int b = blockIdx.x, t = threadIdx.x;  // 256
    for (int j = t; j < cIF; j += 256) sv[j] = g_itf[(size_t)b * cIF + j] + b_if[j];
    __syncthreads();
    float wg = sigmoidf_(sv[256]);
    if (t == 0) { g_wg[b] = wg; g_ag[b] = sigmoidf_(sv[257]); }
    if (t >= 128 && t < 132) {     // softmax over 3 read modes, r = t-128
        int r = t - 128;
        const float* pm = &sv[259 + r * 3];
        float m = fmaxf(pm[0], fmaxf(pm[1], pm[2]));
        float e0 = expf(pm[0] - m), e1 = expf(pm[1] - m), e2 = expf(pm[2] - m);
        float inv = 1.0f / (e0 + e1 + e2);
        g_rm[b * 12 + r * 3 + 0] = e0 * inv;
        g_rm[b * 12 + r * 3 + 1] = e1 * inv;
        g_rm[b * 12 + r * 3 + 2] = e2 * inv;
    }
    if (t >= 136 && t < 140) srstr[t - 136] = softplusf_(sv[271 + (t - 136)]);
    // write values norm + evav (threads 0-127)
    float wv = 0.f;
    if (t < 128) {
        wv = sv[t];
        float er = sigmoidf_(sv[128 + t]);
        g_evav[b * 256 + t] = er * wg;
        g_evav[b * 256 + 128 + t] = wv * wg;
        float sq = wv * wv;
#pragma unroll
        for (int o = 16; o; o >>= 1) sq += __shfl_xor_sync(0xffffffffu, sq, o);
        if ((t & 31) == 0) red[t >> 5] = sq;
    }
    __syncthreads();
    if (t < 128) {
        float tot = red[0] + red[1] + red[2] + red[3];
        g_wvn[b * cD + t] = wv / fmaxf(sqrtf(tot), 1e-12f);
    }
    __syncthreads();
    // keys: 4 rows of 128, two iterations of 2 rows
#pragma unroll
    for (int it = 0; it < 2; it++) {
        int r = it * 2 + (t >> 7);
        int d = t & 127;
        float kv = sv[275 + r * 128 + d];
        float sq = kv * kv;
#pragma unroll
        for (int o = 16; o; o >>= 1) sq += __shfl_xor_sync(0xffffffffu, sq, o);
        if ((t & 31) == 0) red[t >> 5] = sq;
        __syncthreads();
        int base = (t >> 7) * 4;
        float tot = red[base] + red[base + 1] + red[base + 2] + red[base + 3];
        g_keys[((size_t)b * 4 + r) * cD + d] = kv / fmaxf(sqrtf(tot), 1e-12f) * srstr[r];
        __syncthreads();
    }
}

// row softmax over 2048 columns (in place), one block per row
__global__ void k_softmax2048(float* __restrict__ X) {
    float* p = X + (size_t)blockIdx.x * cN;
    int t = threadIdx.x;  // 256
    float v[8];
    float mx = -3.4e38f;
#pragma unroll
    for (int i = 0; i < 8; i++) { v[i] = p[t + 256 * i]; mx = fmaxf(mx, v[i]); }
#pragma unroll
    for (int o = 16; o; o >>= 1) mx = fmaxf(mx, __shfl_xor_sync(0xffffffffu, mx, o));
    __shared__ float sh[8];
    __shared__ float bc;
    if ((t & 31) == 0) sh[t >> 5] = mx;
    __syncthreads();
    if (t == 0) { float m = sh[0]; for (int i = 1; i < 8; i++) m = fmaxf(m, sh[i]); bc = m; }
    __syncthreads();
    mx = bc;
    float s = 0.f;
#pragma unroll
    for (int i = 0; i < 8; i++) { v[i] = expf(v[i] - mx); s += v[i]; }
#pragma unroll
    for (int o = 16; o; o >>= 1) s += __shfl_xor_sync(0xffffffffu, s, o);
    __syncthreads();
    if ((t & 31) == 0) sh[t >> 5] = s;
    __syncthreads();
    if (t == 0) { float m = 0.f; for (int i = 0; i < 8; i++) m += sh[i]; bc = m; }
    __syncthreads();
    float inv = 1.0f / bc;
#pragma unroll
    for (int i = 0; i < 8; i++) p[t + 256 * i] = v[i] * inv;
}

// fused: write weights + row sum S[b]  (block per b)
__global__ void k_writew_S() {
    int b = blockIdx.x, t = threadIdx.x;  // 256
    float wg = g_wg[b], ag = g_ag[b];
    float s = 0.f;
#pragma unroll
    for (int i = 0; i < 8; i++) {
        int n = t + i * 256;
        float w = wg * (0.5f * g_cw[(size_t)b * cN + n] + 0.5f * g_alloc[n] * ag);
        g_ww[(size_t)b * cN + n] = w;
        s += w;
    }
#pragma unroll
    for (int o = 16; o; o >>= 1) s += __shfl_xor_sync(0xffffffffu, s, o);
    __shared__ float sh[8];
    if ((t & 31) == 0) sh[t >> 5] = s;
    __syncthreads();
    if (t == 0) { float m = 0.f; for (int i = 0; i < 8; i++) m += sh[i]; g_S[b] = m; }
}

// fused: t1/t2 statistics + backward/forward vectors
__global__ void k_t12bf() {
    int m = blockIdx.x * blockDim.x + threadIdx.x;
    if (m >= cN) return;
    float t1 = 0.f, t2 = 0.f;
    for (int b = 0; b < cB; b++) {
        float w = g_ww[(size_t)b * cN + m];
        t1 += w * g_S[b];
        t2 += w * w;
    }
    float lu = 0.1f * (t1 - t2) * (1.0f / (float)cB);
    g_bvec[m] = (0.9f * g_colsum[m] + lu) * (1.0f / (float)cN);
    g_fvec[m] = (0.9f * g_rowsum[m] + lu) * (1.0f / (float)cN);
}

// combined transpose of ww (256x2048) and evav (256x256); 1D block of 256
__global__ void k_transWE() {
    __shared__ float tile[32][33];
    int blk = blockIdx.x;
    int tx = threadIdx.x & 31, ty = threadIdx.x >> 5;  // (32, 8)
    const float* in; float* out; int rows, cols, bx, by;
    if (blk < 512) { in = g_ww;   out = g_wwT;   rows = cB; cols = cN;  bx = blk & 63; by = blk >> 6; }
    else { blk -= 512; in = g_evav; out = g_evavT; rows = cB; cols = 256; bx = blk & 7;  by = blk >> 3; }
    int c0 = bx * 32, r0 = by * 32;
#pragma unroll
    for (int i = 0; i < 32; i += 8)
        tile[ty + i][tx] = in[(size_t)(r0 + ty + i) * cols + c0 + tx];
    __syncthreads();
#pragma unroll
    for (int i = 0; i < 32; i += 8)
        out[(size_t)(c0 + ty + i) * rows + r0 + tx] = tile[tx][ty + i];
}

// generic transpose (for memnew -> memnewT)
__global__ void k_transpose(const float* __restrict__ in, float* __restrict__ out,
                            int rows, int cols) {
    __shared__ float tile[32][33];
    int c0 = blockIdx.x * 32, r0 = blockIdx.y * 32;
    int tx = threadIdx.x & 31, ty = threadIdx.x >> 5;
#pragma unroll
    for (int i = 0; i < 32; i += 8)
        tile[ty + i][tx] = in[(size_t)(r0 + ty + i) * cols + c0 + tx];
    __syncthreads();
#pragma unroll
    for (int i = 0; i < 32; i += 8)
        out[(size_t)(c0 + ty + i) * rows + r0 + tx] = tile[tx][ty + i];
}

// fused: mem_new compute + row-normalize; 2 rows per block
__global__ void k_memupd_norm(const float* __restrict__ memory) {
    __shared__ float sh[8];
    int t = threadIdx.x;  // 256
    int rb = blockIdx.x * 2 + (t >> 7);
    int d = t & 127;
    const float inv = 1.0f / (float)cB;
    float e = g_eamat[(size_t)rb * 256 + d];
    float a = g_eamat[(size_t)rb * 256 + cD + d];
    float m = memory[(size_t)rb * cD + d] * (1.0f - e * inv) + a * inv;
    g_memnew[(size_t)rb * cD + d] = m;
    float sq = m * m;
#pragma unroll
    for (int o = 16; o; o >>= 1) sq += __shfl_xor_sync(0xffffffffu, sq, o);
    if ((t & 31) == 0) sh[t >> 5] = sq;
    __syncthreads();
    int base = (t >> 7) * 4;
    float tot = sh[base] + sh[base + 1] + sh[base + 2] + sh[base + 3];
    g_memnewn[(size_t)rb * cD + d] = m / fmaxf(sqrtf(tot), 1e-12f);
}

__global__ void k_bmfm() {
    int t = threadIdx.x;        // 128
    int r0 = blockIdx.x * 64;   // 32 blocks
    float sb = 0.f, sf = 0.f;
    for (int r = 0; r < 64; r++) {
        float m = g_memnew[(size_t)(r0 + r) * cD + t];
        sb += g_bvec[r0 + r] * m;
        sf += g_fvec[r0 + r] * m;
    }
    atomicAdd(&g_bm[t], sb);
    atomicAdd(&g_fm[t], sf);
}

// fill g_cat[:, 1024:1536] with combined readout
__global__ void k_readout() {
    int idx = blockIdx.x * blockDim.x + threadIdx.x;  // B*R*D
    if (idx >= cB * cR * cD) return;
    int br = idx >> 7, d = idx & (cD - 1);
    int b = br >> 2, r = br & 3;
    const float* rm = g_rm + br * 3;
    float v = rm[0] * g_readc[(size_t)br * cD + d] + rm[1] * g_bm[d] + rm[2] * g_fm[d];
    g_cat[(size_t)b * cOPI + cH + r * cD + d] = v;
}

// ================= host launch =================
static void* symaddr(const void* sym) { void* p = nullptr; cudaGetSymbolAddress(&p, sym); return p; }

extern "C" void kernel_launch(void* const* d_in, const int* in_sizes, int n_in,
                              void* d_out, int out_size) {
    const float* x      = (const float*)d_in[0];
    const float* memory = (const float*)d_in[1];
    const float* usage  = (const float*)d_in[2];
    const float* link   = (const float*)d_in[3];
    const float* W_ih   = (const float*)d_in[4];
    const float* b_ih   = (const float*)d_in[6];
    const float* b_hh   = (const float*)d_in[7];
    const float* W_if   = (const float*)d_in[8];
    const float* b_if   = (const float*)d_in[9];
    const float* W_out  = (const float*)d_in[10];
    const float* b_out  = (const float*)d_in[11];
    float* out = (float*)d_out;

    float* p_graw    = (float*)symaddr(g_graw);
    float* p_itf     = (float*)symaddr(g_itf);
    float* p_wvn     = (float*)symaddr(g_wvn);
    float* p_memn    = (float*)symaddr(g_memn);
    float* p_cw      = (float*)symaddr(g_cw);
    float* p_wwT     = (float*)symaddr(g_wwT);
    float* p_evavT   = (float*)symaddr(g_evavT);
    float* p_eamat   = (float*)symaddr(g_eamat);
    float* p_memnewn = (float*)symaddr(g_memnewn);
    float* p_memnewT = (float*)symaddr(g_memnewT);
    float* p_keys    = (float*)symaddr(g_keys);
    float* p_L       = (float*)symaddr(g_L);
    float* p_readc   = (float*)symaddr(g_readc);
    float* p_cat     = (float*)symaddr(g_cat);
    float* p_meanm   = (float*)symaddr(g_mean_mem);
    float* p_colsum  = (float*)symaddr(g_colsum);
    float* p_bm      = (float*)symaddr(g_bm);
    float* p_fm      = (float*)symaddr(g_fm);

    cudaFuncSetAttribute(mma_nt<1, false>, cudaFuncAttributeMaxDynamicSharedMemorySize, MMA_SMEM);
    cudaFuncSetAttribute(mma_nt<4, true>,  cudaFuncAttributeMaxDynamicSharedMemorySize, MMA_SMEM);
    cudaFuncSetAttribute(mma_nt<8, true>,  cudaFuncAttributeMaxDynamicSharedMemorySize, MMA_SMEM);

    // zero accumulators / atomic targets
    cudaMemsetAsync(p_meanm, 0, cD * sizeof(float));
    cudaMemsetAsync(p_colsum, 0, cN * sizeof(float));
    cudaMemsetAsync(p_bm, 0, cD * sizeof(float));
    cudaMemsetAsync(p_fm, 0, cD * sizeof(float));
    cudaMemsetAsync(p_itf, 0, cB * cIF * sizeof(float));
    cudaMemsetAsync(p_readc, 0, cB * cR * cD * sizeof(float));
    cudaMemsetAsync(out, 0, cB * cH * sizeof(float));

    // stage 0
    k_mem_mean<<<32, 256>>>(memory);
    k_stage0<<<S0_END, 256>>>(memory, link, usage, W_ih);

    // controller LSTM: graw = x @ W_ih[:, :1024]^T
    mma_nt<1, false><<<dim3(cG / 64, cB / 128, 1), 256, MMA_SMEM>>>(
        x, cI, W_ih, cCI, nullptr, p_graw, cG, cB, cG, cI);
    k_scan<<<1, 1024>>>();   // hidden behind graw's tail; needed only by k_writew_S
    k_gates<<<(cB * cH + 255) / 256, 256>>>(b_ih, b_hh);

    // interface: itf = h @ W_if^T   (split-K atomic; A = g_cat rows, lda=cOPI)
    mma_nt<4, true><<<dim3((cIF + 63) / 64, cB / 128, 4), 256, MMA_SMEM>>>(
        p_cat, cOPI, W_if, cH, nullptr, p_itf, cIF, cB, cIF, cH);
    k_parse_fused<<<cB, 256>>>(b_if);

    // content write addressing: cw = wvn @ memn^T
    mma_nt<1, false><<<dim3(cN / 64, cB / 128, 1), 256, MMA_SMEM>>>(
        p_wvn, cD, p_memn, cD, nullptr, p_cw, cN, cB, cN, cD);
    k_softmax2048<<<cB, 256>>>(p_cw);

    // write weights + link-mean statistics
    k_writew_S<<<cB, 256>>>();
    k_transWE<<<576, 256>>>();
    k_t12bf<<<(cN + 255) / 256, 256>>>();

    // memory update: eamat = ww^T @ [ev|av]
    mma_nt<1, false><<<dim3(2 * cD / 64, cN / 128, 1), 256, MMA_SMEM>>>(
        p_wwT, cB, p_evavT, cB, nullptr, p_eamat, 2 * cD, cN, 2 * cD, cB);
    k_memupd_norm<<<cN / 2, 256>>>(memory);
    k_bmfm<<<32, 128>>>();
    k_transpose<<<dim3(cD / 32, cN / 32), 256>>>((const float*)symaddr(g_memnew), p_memnewT, cN, cD);

    // read addressing: L = keys @ memnewn^T ; readc = L @ memnewT^T (split-K)
    mma_nt<1, false><<<dim3(cN / 64, (cB * cR) / 128, 1), 256, MMA_SMEM>>>(
        p_keys, cD, p_memnewn, cD, nullptr, p_L, cN, cB * cR, cN, cD);
    k_softmax2048<<<cB * cR, 256>>>(p_L);
    mma_nt<8, true><<<dim3(cD / 64, (cB * cR) / 128, 8), 256, MMA_SMEM>>>(
        p_L, cN, p_memnewT, cN, nullptr, p_readc, cD, cB * cR, cD, cN);

    // readout + output projection
    k_readout<<<(cB * cR * cD + 255) / 256, 256>>>();
    mma_nt<4, true><<<dim3(cH / 64, cB / 128, 4), 256, MMA_SMEM>>>(
        p_cat, cOPI, W_out, cOPI, b_out, out, cH, cB, cH, cOPI);
}

// round 11
// speedup vs baseline: 1.0071x; 1.0071x over previous
#include <cuda_runtime.h>
#include <math.h>
#include <stdint.h>

// ---------------- problem dims ----------------
#define cB   256
#define cN   2048
#define cD   128
#define cR   4
#define cH   1024
#define cI   1024
#define cCI  1536
#define cIF  787
#define cOPI 1536
#define cG   4096   // 4*H

// ---------------- scratch (device globals) ----------------
__device__ float g_mean_mem[cD];
__device__ float g_v[cG];
__device__ float g_graw[cB * cG];
__device__ float g_itf[cB * cIF];
__device__ float g_wvn[cB * cD];
__device__ float g_wg[cB];
__device__ float g_ag[cB];
__device__ float g_rm[cB * cR * 3];
__device__ float g_keys[cB * cR * cD];
__device__ float g_memn[cN * cD];
__device__ float g_cw[cB * cN];
__device__ float g_alloc[cN];
__device__ float g_sorted[cN];
__device__ int   g_sidx[cN];
__device__ float g_ww[cB * cN];
__device__ float g_wwT[cN * cB];
__device__ float g_S[cB];
__device__ float g_rowsum[cN];
__device__ float g_colsum[cN];
__device__ float g_bvec[cN];
__device__ float g_fvec[cN];
__device__ float g_evav[cB * 2 * cD];     // [b][0:128)=ev, [128:256)=av
__device__ float g_evavT[2 * cD * cB];
__device__ float g_eamat[cN * 2 * cD];    // [n][0:128)=emat, [128:256)=amat
__device__ float g_memnew[cN * cD];
__device__ float g_memnewn[cN * cD];
__device__ float g_memnewT[cD * cN];
__device__ float g_bm[cD];
__device__ float g_fm[cD];
__device__ float g_L[cB * cR * cN];
__device__ float g_readc[cB * cR * cD];
__device__ float g_cat[cB * cOPI];        // [h | readout]

// ---------------- helpers ----------------
__device__ __forceinline__ float sigmoidf_(float x) { return 1.0f / (1.0f + expf(-x)); }
__device__ __forceinline__ float softplusf_(float x) { return x > 20.0f ? x : log1pf(expf(x)); }
__device__ __forceinline__ uint32_t f2tf32(float f) {
    uint32_t u; asm("cvt.rna.tf32.f32 %0, %1;" : "=r"(u) : "f"(f)); return u;
}
__device__ __forceinline__ void mma8(float* c, const uint32_t* a, const uint32_t* b) {
    asm volatile(
        "mma.sync.aligned.m16n8k8.row.col.f32.tf32.tf32.f32 "
        "{%0,%1,%2,%3},{%4,%5,%6,%7},{%8,%9},{%0,%1,%2,%3};"
        : "+f"(c[0]), "+f"(c[1]), "+f"(c[2]), "+f"(c[3])
        : "r"(a[0]), "r"(a[1]), "r"(a[2]), "r"(a[3]), "r"(b[0]), "r"(b[1]));
}

// ================= tf32 tensor-core GEMM (nt): C[M,N] = A[M,K] . B[N,K]^T =================
#define MMA_SMEM (2*(128*36 + 64*36)*4)

template<int SPLITK, bool ATOMIC>
__global__ void mma_nt(const float* __restrict__ A, int lda,
                       const float* __restrict__ Bm, int ldb,
                       const float* __restrict__ bias,
                       float* __restrict__ C, int ldc,
                       int M, int N, int K)
{
    extern __shared__ float sm_[];
    float* As = sm_;                 // [2][128][36]
    float* Bs = sm_ + 2 * 128 * 36;  // [2][64][36]
    const int t = threadIdx.x;
    const int lane = t & 31;
    const int w = t >> 5;
    const int grp = lane >> 2, tg = lane & 3;
    const int wm = w & 3, wn = w >> 2;
    const int m0 = blockIdx.y * 128, n0 = blockIdx.x * 64;
    const int Kc = K / SPLITK;
    const int kstart = blockIdx.z * Kc;
    const int KT = Kc / 32;

    const uint32_t sA = (uint32_t)__cvta_generic_to_shared(As);
    const uint32_t sB = (uint32_t)__cvta_generic_to_shared(Bs);
    const int lr = t >> 3, lc = (t & 7) * 4;

    float acc[2][4][4];
#pragma unroll
    for (int mi = 0; mi < 2; mi++)
#pragma unroll
        for (int ni = 0; ni < 4; ni++)
#pragma unroll
            for (int k = 0; k < 4; k++) acc[mi][ni][k] = 0.f;

    auto load_stage = [&](int st, int kb) {
#pragma unroll
        for (int i = 0; i < 4; i++) {
            int row = lr + 32 * i;
            const float* g = A + (size_t)(m0 + row) * lda + kb + lc;
            uint32_t d = sA + (uint32_t)((st * 4608 + row * 36 + lc) * 4);
            asm volatile("cp.async.ca.shared.global [%0],[%1],16,%2;" :: "r"(d), "l"(g), "r"(16));
        }
#pragma unroll
        for (int i = 0; i < 2; i++) {
            int row = lr + 32 * i;
            const float* g = Bm + (size_t)(n0 + row) * ldb + kb + lc;
            uint32_t d = sB + (uint32_t)((st * 2304 + row * 36 + lc) * 4);
            int sz = (n0 + row < N) ? 16 : 0;
            asm volatile("cp.async.ca.shared.global [%0],[%1],16,%2;" :: "r"(d), "l"(g), "r"(sz));
        }
        asm volatile("cp.async.commit_group;");
    };

    auto compute = [&](int st) {
        const float* Ab = As + st * 4608;
        const float* Bb = Bs + st * 2304;
#pragma unroll
        for (int ko = 0; ko < 32; ko += 8) {
            uint32_t af[2][4], bf[4][2];
#pragma unroll
            for (int mi = 0; mi < 2; mi++) {
                int rb = wm * 32 + mi * 16;
                af[mi][0] = f2tf32(Ab[(rb + grp) * 36 + ko + tg]);
                af[mi][1] = f2tf32(Ab[(rb + grp + 8) * 36 + ko + tg]);
                af[mi][2] = f2tf32(Ab[(rb + grp) * 36 + ko + tg + 4]);
                af[mi][3] = f2tf32(Ab[(rb + grp + 8) * 36 + ko + tg + 4]);
            }
#pragma unroll
            for (int ni = 0; ni < 4; ni++) {
                int nb = wn * 32 + ni * 8 + grp;
                bf[ni][0] = f2tf32(Bb[nb * 36 + ko + tg]);
                bf[ni][1] = f2tf32(Bb[nb * 36 + ko + tg + 4]);
            }
#pragma unroll
            for (int mi = 0; mi < 2; mi++)
#pragma unroll
                for (int ni = 0; ni < 4; ni++) mma8(acc[mi][ni], af[mi], bf[ni]);
        }
    };

    load_stage(0, kstart);
    for (int kt = 0; kt < KT; kt++) {
        if (kt + 1 < KT) {
            load_stage((kt + 1) & 1, kstart + (kt + 1) * 32);
            asm volatile("cp.async.wait_group 1;");
        } else {
            asm volatile("cp.async.wait_group 0;");
        }
        __syncthreads();
        compute(kt & 1);
        __syncthreads();
    }

    const bool addb = (bias != nullptr) && (SPLITK == 1 || blockIdx.z == 0);
#pragma unroll
    for (int mi = 0; mi < 2; mi++) {
        int r_ = m0 + wm * 32 + mi * 16 + grp;
#pragma unroll
        for (int ni = 0; ni < 4; ni++) {
            int c_ = n0 + wn * 32 + ni * 8 + tg * 2;
            float b0 = (addb && c_ < N) ? bias[c_] : 0.f;
            float b1 = (addb && c_ + 1 < N) ? bias[c_ + 1] : 0.f;
            float* cp0 = C + (size_t)r_ * ldc + c_;
            float* cp1 = C + (size_t)(r_ + 8) * ldc + c_;
            if (ATOMIC) {
                if (c_ < N)     { atomicAdd(cp0,     acc[mi][ni][0] + b0);
                                  atomicAdd(cp1,     acc[mi][ni][2] + b0); }
                if (c_ + 1 < N) { atomicAdd(cp0 + 1, acc[mi][ni][1] + b1);
                                  atomicAdd(cp1 + 1, acc[mi][ni][3] + b1); }
            } else {
                if (c_ < N)     { cp0[0] = acc[mi][ni][0] + b0;
                                  cp1[0] = acc[mi][ni][2] + b0; }
                if (c_ + 1 < N) { cp0[1] = acc[mi][ni][1] + b1;
                                  cp1[1] = acc[mi][ni][3] + b1; }
            }
        }
    }
}

// ================= small kernels =================

// column mean of memory (before stage0; k_v depends on it)
__global__ void k_mem_mean(const float* __restrict__ memory) {
    int t = threadIdx.x;              // 256: d = t&127, half = t>>7
    int d = t & 127;
    int r0 = blockIdx.x * 64 + (t >> 7);   // 32 blocks
    float s = 0.f;
    for (int r = 0; r < 32; r++) s += memory[(size_t)(r0 + r * 2) * cD + d];
    atomicAdd(&g_mean_mem[d], s * (1.0f / (float)cN));
}

// fused stage-0: rank | memn | link rowsum | link colsum | v
#define S0_RANK 0
#define S0_NORM 256
#define S0_ROWS 1280
#define S0_COLS 1536
#define S0_V    1664
#define S0_END  2176
__global__ void k_stage0(const float* __restrict__ memory,
                         const float* __restrict__ link,
                         const float* __restrict__ usage,
                         const float* __restrict__ W_ih) {
    __shared__ float sh[8];
    int blk = blockIdx.x, t = threadIdx.x;
    int w = t >> 5, lane = t & 31;
    if (blk < S0_NORM) {
        // rank: warp per element (stable ascending)
        int e = blk * 8 + w;
        float u = usage[e];
        int r = 0;
        for (int j = lane; j < cN; j += 32) {
            float uj = usage[j];
            r += (uj < u) || (uj == u && j < e);
        }
#pragma unroll
        for (int o = 16; o; o >>= 1) r += __shfl_xor_sync(0xffffffffu, r, o);
        if (lane == 0) { g_sorted[r] = u; g_sidx[r] = e; }
    } else if (blk < S0_ROWS) {
        // normalize memory rows: 2 rows per block
        int rb = (blk - S0_NORM) * 2 + (t >> 7);
        int d = t & 127;
        float v = memory[(size_t)rb * cD + d];
        float sq = v * v;
#pragma unroll
        for (int o = 16; o; o >>= 1) sq += __shfl_xor_sync(0xffffffffu, sq, o);
        if (lane == 0) sh[w] = sq;
        __syncthreads();
        int base = (t >> 7) * 4;
        float tot = sh[base] + sh[base + 1] + sh[base + 2] + sh[base + 3];
        g_memn[(size_t)rb * cD + d] = v / fmaxf(sqrtf(tot), 1e-12f);
    } else if (blk < S0_COLS) {
        // link row sums: warp per row
        int row = (blk - S0_ROWS) * 8 + w;
        const float* p = link + (size_t)row * cN;
        float s = 0.f;
        for (int j = lane; j < cN; j += 32) s += p[j];
#pragma unroll
        for (int o = 16; o; o >>= 1) s += __shfl_xor_sync(0xffffffffu, s, o);
        if (lane == 0) g_rowsum[row] = s;
    } else if (blk < S0_V) {
        // link col sums: 128 blocks (16 row-chunks x 8 col-chunks)
        int rc = blk - S0_COLS;
        int rchunk = rc >> 3, cchunk = rc & 7;
        int col = cchunk * 256 + t;
        const float* p = link + (size_t)(rchunk * 128) * cN + col;
        float acc = 0.f;
        for (int r = 0; r < 128; r++) acc += p[(size_t)r * cN];
        atomicAdd(&g_colsum[col], acc);
    } else {
        // v[j] = mean_mem (tiled x4) . W_ih[j, 1024:1536]
        int gw = (blk - S0_V) * 8 + w;
        const float* wr = W_ih + (size_t)gw * cCI + cI;
        float a = 0.f;
        for (int k = lane; k < cR * cD; k += 32) a += g_mean_mem[k & (cD - 1)] * wr[k];
#pragma unroll
        for (int o = 16; o; o >>= 1) a += __shfl_xor_sync(0xffffffffu, a, o);
        if (lane == 0) g_v[gw] = a;
    }
}

// two-level multiplicative scan over sorted usage; scatter alloc
__global__ void k_scan() {
    __shared__ float wtot[32];
    int t = threadIdx.x;  // 1024
    int lane = t & 31, wid = t >> 5;
    float u0 = g_sorted[2 * t], u1 = g_sorted[2 * t + 1];
    float v0 = 1.0f - u0, v1 = 1.0f - u1;
    float p = v0 * v1;
    float sp = p;  // inclusive scan of pair products within warp
#pragma unroll
    for (int o = 1; o < 32; o <<= 1) {
        float n = __shfl_up_sync(0xffffffffu, sp, o);
        if (lane >= o) sp *= n;
    }
    if (lane == 31) wtot[wid] = sp;
    __syncthreads();
    if (wid == 0) {
        float wv = wtot[lane];
#pragma unroll
        for (int o = 1; o < 32; o <<= 1) {
            float n = __shfl_up_sync(0xffffffffu, wv, o);
            if (lane >= o) wv *= n;
        }
        wtot[lane] = wv;
    }
    __syncthreads();
    float eincl = __shfl_up_sync(0xffffffffu, sp, 1);     // exclusive pair prefix (within warp)
    float epair = (lane == 0) ? 1.0f : eincl;
    float wpre = (wid == 0) ? 1.0f : wtot[wid - 1];
    float E0 = wpre * epair;          // prod of (1-u) before index 2t
    float E1 = E0 * v0;               // before index 2t+1
    g_alloc[g_sidx[2 * t]]     = u0 * E0;
    g_alloc[g_sidx[2 * t + 1]] = u1 * E1;
}

// LSTM gates -> h written straight into g_cat[:, 0:1024]
__global__ void k_gates(const float* __restrict__ b_ih, const float* __restrict__ b_hh) {
    int idx = blockIdx.x * blockDim.x + threadIdx.x;
    if (idx >= cB * cH) return;
    int b = idx >> 10, j = idx & (cH - 1);
    const float* gr = g_graw + (size_t)b * cG;
    float gi = gr[j]          + b_ih[j]          + b_hh[j]          + g_v[j];
    float gg = gr[j + 2 * cH] + b_ih[j + 2 * cH] + b_hh[j + 2 * cH] + g_v[j + 2 * cH];
    float go = gr[j + 3 * cH] + b_ih[j + 3 * cH] + b_hh[j + 3 * cH] + g_v[j + 3 * cH];
    float c = sigmoidf_(gi) * tanhf(gg);
    g_cat[(size_t)b * cOPI + j] = sigmoidf_(go) * tanhf(c);
}

// fused: parse + softmax3 + wv-norm + key-norms(+strength) + evav; one block per b
__global__ void k_parse_fused(const float* __restrict__ b_if) {
    __shared__ float sv[cIF];
    __shared__ float red[8];
    __shared__ float srstr[4];
    int b = blockIdx.x, t = threadIdx.x;  // 256
    for (int j = t; j < cIF; j += 256) sv[j] = g_itf[(size_t)b * cIF + j] + b_if[j];
    __syncthreads();
    float wg = sigmoidf_(sv[256]);
    if (t == 0) { g_wg[b] = wg; g_ag[b] = sigmoidf_(sv[257]); }
    if (t >= 128 && t < 132) {     // softmax over 3 read modes, r = t-128
        int r = t - 128;
        const float* pm = &sv[259 + r * 3];
        float m = fmaxf(pm[0], fmaxf(pm[1], pm[2]));
        float e0 = expf(pm[0] - m), e1 = expf(pm[1] - m), e2 = expf(pm[2] - m);
        float inv = 1.0f / (e0 + e1 + e2);
        g_rm[b * 12 + r * 3 + 0] = e0 * inv;
        g_rm[b * 12 + r * 3 + 1] = e1 * inv;
        g_rm[b * 12 + r * 3 + 2] = e2 * inv;
    }
    if (t >= 136 && t < 140) srstr[t - 136] = softplusf_(sv[271 + (t - 136)]);
    // write values norm + evav (threads 0-127)
    float wv = 0.f;
    if (t < 128) {
        wv = sv[t];
        float er = sigmoidf_(sv[128 + t]);
        g_evav[b * 256 + t] = er * wg;
        g_evav[b * 256 + 128 + t] = wv * wg;
        float sq = wv * wv;
#pragma unroll
        for (int o = 16; o; o >>= 1) sq += __shfl_xor_sync(0xffffffffu, sq, o);
        if ((t & 31) == 0) red[t >> 5] = sq;
    }
    __syncthreads();
    if (t < 128) {
        float tot = red[0] + red[1] + red[2] + red[3];
        g_wvn[b * cD + t] = wv / fmaxf(sqrtf(tot), 1e-12f);
    }
    __syncthreads();
    // keys: 4 rows of 128, two iterations of 2 rows
#pragma unroll
    for (int it = 0; it < 2; it++) {
        int r = it * 2 + (t >> 7);
        int d = t & 127;
        float kv = sv[275 + r * 128 + d];
        float sq = kv * kv;
#pragma unroll
        for (int o = 16; o; o >>= 1) sq += __shfl_xor_sync(0xffffffffu, sq, o);
        if ((t & 31) == 0) red[t >> 5] = sq;
        __syncthreads();
        int base = (t >> 7) * 4;
        float tot = red[base] + red[base + 1] + red[base + 2] + red[base + 3];
        g_keys[((size_t)b * 4 + r) * cD + d] = kv / fmaxf(sqrtf(tot), 1e-12f) * srstr[r];
        __syncthreads();
    }
}

// row softmax over 2048 columns (in place), one block per row
__global__ void k_softmax2048(float* __restrict__ X) {
    float* p = X + (size_t)blockIdx.x * cN;
    int t = threadIdx.x;  // 256
    float v[8];
    float mx = -3.4e38f;
#pragma unroll
    for (int i = 0; i < 8; i++) { v[i] = p[t + 256 * i]; mx = fmaxf(mx, v[i]); }
#pragma unroll
    for (int o = 16; o; o >>= 1) mx = fmaxf(mx, __shfl_xor_sync(0xffffffffu, mx, o));
    __shared__ float sh[8];
    __shared__ float bc;
    if ((t & 31) == 0) sh[t >> 5] = mx;
    __syncthreads();
    if (t == 0) { float m = sh[0]; for (int i = 1; i < 8; i++) m = fmaxf(m, sh[i]); bc = m; }
    __syncthreads();
    mx = bc;
    float s = 0.f;
#pragma unroll
    for (int i = 0; i < 8; i++) { v[i] = expf(v[i] - mx); s += v[i]; }
#pragma unroll
    for (int o = 16; o; o >>= 1) s += __shfl_xor_sync(0xffffffffu, s, o);
    __syncthreads();
    if ((t & 31) == 0) sh[t >> 5] = s;
    __syncthreads();
    if (t == 0) { float m = 0.f; for (int i = 0; i < 8; i++) m += sh[i]; bc = m; }
    __syncthreads();
    float inv = 1.0f / bc;
#pragma unroll
    for (int i = 0; i < 8; i++) p[t + 256 * i] = v[i] * inv;
}

// fused: write weights + row sum S[b]  (block per b)
__global__ void k_writew_S() {
    int b = blockIdx.x, t = threadIdx.x;  // 256
    float wg = g_wg[b], ag = g_ag[b];
    float s = 0.f;
#pragma unroll
    for (int i = 0; i < 8; i++) {
        int n = t + i * 256;
        float w = wg * (0.5f * g_cw[(size_t)b * cN + n] + 0.5f * g_alloc[n] * ag);
        g_ww[(size_t)b * cN + n] = w;
        s += w;
    }
#pragma unroll
    for (int o = 16; o; o >>= 1) s += __shfl_xor_sync(0xffffffffu, s, o);
    __shared__ float sh[8];
    if ((t & 31) == 0) sh[t >> 5] = s;
    __syncthreads();
    if (t == 0) { float m = 0.f; for (int i = 0; i < 8; i++) m += sh[i]; g_S[b] = m; }
}

// fused: t1/t2 statistics + backward/forward vectors
__global__ void k_t12bf() {
    int m = blockIdx.x * blockDim.x + threadIdx.x;
    if (m >= cN) return;
    float t1 = 0.f, t2 = 0.f;
    for (int b = 0; b < cB; b++) {
        float w = g_ww[(size_t)b * cN + m];
        t1 += w * g_S[b];
        t2 += w * w;
    }
    float lu = 0.1f * (t1 - t2) * (1.0f / (float)cB);
    g_bvec[m] = (0.9f * g_colsum[m] + lu) * (1.0f / (float)cN);
    g_fvec[m] = (0.9f * g_rowsum[m] + lu) * (1.0f / (float)cN);
}

// combined transpose of ww (256x2048) and evav (256x256); 1D block of 256
__global__ void k_transWE() {
    __shared__ float tile[32][33];
    int blk = blockIdx.x;
    int tx = threadIdx.x & 31, ty = threadIdx.x >> 5;  // (32, 8)
    const float* in; float* out; int rows, cols, bx, by;
    if (blk < 512) { in = g_ww;   out = g_wwT;   rows = cB; cols = cN;  bx = blk & 63; by = blk >> 6; }
    else { blk -= 512; in = g_evav; out = g_evavT; rows = cB; cols = 256; bx = blk & 7;  by = blk >> 3; }
    int c0 = bx * 32, r0 = by * 32;
#pragma unroll
    for (int i = 0; i < 32; i += 8)
        tile[ty + i][tx] = in[(size_t)(r0 + ty + i) * cols + c0 + tx];
    __syncthreads();
#pragma unroll
    for (int i = 0; i < 32; i += 8)
        out[(size_t)(c0 + ty + i) * rows + r0 + tx] = tile[tx][ty + i];
}

// generic transpose (for memnew -> memnewT)
__global__ void k_transpose(const float* __restrict__ in, float* __restrict__ out,
                            int rows, int cols) {
    __shared__ float tile[32][33];
    int c0 = blockIdx.x * 32, r0 = blockIdx.y * 32;
    int tx = threadIdx.x & 31, ty = threadIdx.x >> 5;
#pragma unroll
    for (int i = 0; i < 32; i += 8)
        tile[ty + i][tx] = in[(size_t)(r0 + ty + i) * cols + c0 + tx];
    __syncthreads();
#pragma unroll
    for (int i = 0; i < 32; i += 8)
        out[(size_t)(c0 + ty + i) * rows + r0 + tx] = tile[tx][ty + i];
}

// fused: mem_new compute + row-normalize; 2 rows per block
__global__ void k_memupd_norm(const float* __restrict__ memory) {
    __shared__ float sh[8];
    int t = threadIdx.x;  // 256
    int rb = blockIdx.x * 2 + (t >> 7);
    int d = t & 127;
    const float inv = 1.0f / (float)cB;
    float e = g_eamat[(size_t)rb * 256 + d];
    float a = g_eamat[(size_t)rb * 256 + cD + d];
    float m = memory[(size_t)rb * cD + d] * (1.0f - e * inv) + a * inv;
    g_memnew[(size_t)rb * cD + d] = m;
    float sq = m * m;
#pragma unroll
    for (int o = 16; o; o >>= 1) sq += __shfl_xor_sync(0xffffffffu, sq, o);
    if ((t & 31) == 0) sh[t >> 5] = sq;
    __syncthreads();
    int base = (t >> 7) * 4;
    float tot = sh[base] + sh[base + 1] + sh[base + 2] + sh[base + 3];
    g_memnewn[(size_t)rb * cD + d] = m / fmaxf(sqrtf(tot), 1e-12f);
}

__global__ void k_bmfm() {
    int t = threadIdx.x;        // 128
    int r0 = blockIdx.x * 64;   // 32 blocks
    float sb = 0.f, sf = 0.f;
    for (int r = 0; r < 64; r++) {
        float m = g_memnew[(size_t)(r0 + r) * cD + t];
        sb += g_bvec[r0 + r] * m;
        sf += g_fvec[r0 + r] * m;
    }
    atomicAdd(&g_bm[t], sb);
    atomicAdd(&g_fm[t], sf);
}

// fill g_cat[:, 1024:1536] with combined readout
__global__ void k_readout() {
    int idx = blockIdx.x * blockDim.x + threadIdx.x;  // B*R*D
    if (idx >= cB * cR * cD) return;
    int br = idx >> 7, d = idx & (cD - 1);
    int b = br >> 2, r = br & 3;
    const float* rm = g_rm + br * 3;
    float v = rm[0] * g_readc[(size_t)br * cD + d] + rm[1] * g_bm[d] + rm[2] * g_fm[d];
    g_cat[(size_t)b * cOPI + cH + r * cD + d] = v;
}

// ================= host launch =================
static void* symaddr(const void* sym) { void* p = nullptr; cudaGetSymbolAddress(&p, sym); return p; }

extern "C" void kernel_launch(void* const* d_in, const int* in_sizes, int n_in,
                              void* d_out, int out_size) {
    const float* x      = (const float*)d_in[0];
    const float* memory = (const float*)d_in[1];
    const float* usage  = (const float*)d_in[2];
    const float* link   = (const float*)d_in[3];
    const float* W_ih   = (const float*)d_in[4];
    const float* b_ih   = (const float*)d_in[6];
    const float* b_hh   = (const float*)d_in[7];
    const float* W_if   = (const float*)d_in[8];
    const float* b_if   = (const float*)d_in[9];
    const float* W_out  = (const float*)d_in[10];
    const float* b_out  = (const float*)d_in[11];
    float* out = (float*)d_out;

    float* p_graw    = (float*)symaddr(g_graw);
    float* p_itf     = (float*)symaddr(g_itf);
    float* p_wvn     = (float*)symaddr(g_wvn);
    float* p_memn    = (float*)symaddr(g_memn);
    float* p_cw      = (float*)symaddr(g_cw);
    float* p_wwT     = (float*)symaddr(g_wwT);
    float* p_evavT   = (float*)symaddr(g_evavT);
    float* p_eamat   = (float*)symaddr(g_eamat);
    float* p_memnewn = (float*)symaddr(g_memnewn);
    float* p_memnewT = (float*)symaddr(g_memnewT);
    float* p_keys    = (float*)symaddr(g_keys);
    float* p_L       = (float*)symaddr(g_L);
    float* p_readc   = (float*)symaddr(g_readc);
    float* p_cat     = (float*)symaddr(g_cat);
    float* p_meanm   = (float*)symaddr(g_mean_mem);
    float* p_colsum  = (float*)symaddr(g_colsum);
    float* p_bm      = (float*)symaddr(g_bm);
    float* p_fm      = (float*)symaddr(g_fm);

    cudaFuncSetAttribute(mma_nt<1, false>, cudaFuncAttributeMaxDynamicSharedMemorySize, MMA_SMEM);
    cudaFuncSetAttribute(mma_nt<4, true>,  cudaFuncAttributeMaxDynamicSharedMemorySize, MMA_SMEM);
    cudaFuncSetAttribute(mma_nt<8, true>,  cudaFuncAttributeMaxDynamicSharedMemorySize, MMA_SMEM);

    // zero accumulators / atomic targets
    cudaMemsetAsync(p_meanm, 0, cD * sizeof(float));
    cudaMemsetAsync(p_colsum, 0, cN * sizeof(float));
    cudaMemsetAsync(p_bm, 0, cD * sizeof(float));
    cudaMemsetAsync(p_fm, 0, cD * sizeof(float));
    cudaMemsetAsync(p_itf, 0, cB * cIF * sizeof(float));
    cudaMemsetAsync(p_readc, 0, cB * cR * cD * sizeof(float));
    cudaMemsetAsync(out, 0, cB * cH * sizeof(float));

    // stage 0
    k_mem_mean<<<32, 256>>>(memory);
    k_stage0<<<S0_END, 256>>>(memory, link, usage, W_ih);

    // controller LSTM: graw = x @ W_ih[:, :1024]^T
    mma_nt<1, false><<<dim3(cG / 64, cB / 128, 1), 256, MMA_SMEM>>>(
        x, cI, W_ih, cCI, nullptr, p_graw, cG, cB, cG, cI);
    k_scan<<<1, 1024>>>();   // hidden behind graw's tail; needed only by k_writew_S
    k_gates<<<(cB * cH + 255) / 256, 256>>>(b_ih, b_hh);

    // interface: itf = h @ W_if^T   (split-K atomic; A = g_cat rows, lda=cOPI)
    mma_nt<4, true><<<dim3((cIF + 63) / 64, cB / 128, 4), 256, MMA_SMEM>>>(
        p_cat, cOPI, W_if, cH, nullptr, p_itf, cIF, cB, cIF, cH);
    k_parse_fused<<<cB, 256>>>(b_if);

    // content write addressing: cw = wvn @ memn^T
    mma_nt<1, false><<<dim3(cN / 64, cB / 128, 1), 256, MMA_SMEM>>>(
        p_wvn, cD, p_memn, cD, nullptr, p_cw, cN, cB, cN, cD);
    k_softmax2048<<<cB, 256>>>(p_cw);

    // write weights + link-mean statistics
    k_writew_S<<<cB, 256>>>();
    k_transWE<<<576, 256>>>();
    k_t12bf<<<(cN + 255) / 256, 256>>>();

    // memory update: eamat = ww^T @ [ev|av]
    mma_nt<1, false><<<dim3(2 * cD / 64, cN / 128, 1), 256, MMA_SMEM>>>(
        p_wwT, cB, p_evavT, cB, nullptr, p_eamat, 2 * cD, cN, 2 * cD, cB);
    k_memupd_norm<<<cN / 2, 256>>>(memory);
    k_bmfm<<<32, 128>>>();
    k_transpose<<<dim3(cD / 32, cN / 32), 256>>>((const float*)symaddr(g_memnew), p_memnewT, cN, cD);

    // read addressing: L = keys @ memnewn^T ; readc = L @ memnewT^T (split-K)
    mma_nt<1, false><<<dim3(cN / 64, (cB * cR) / 128, 1), 256, MMA_SMEM>>>(
        p_keys, cD, p_memnewn, cD, nullptr, p_L, cN, cB * cR, cN, cD);
    k_softmax2048<<<cB * cR, 256>>>(p_L);
    mma_nt<8, true><<<dim3(cD / 64, (cB * cR) / 128, 8), 256, MMA_SMEM>>>(
        p_L, cN, p_memnewT, cN, nullptr, p_readc, cD, cB * cR, cD, cN);

    // readout + output projection
    k_readout<<<(cB * cR * cD + 255) / 256, 256>>>();
    mma_nt<4, true><<<dim3(cH / 64, cB / 128, 4), 256, MMA_SMEM>>>(
        p_cat, cOPI, W_out, cOPI, b_out, out, cH, cB, cH, cOPI);
}